// round 9
// baseline (speedup 1.0000x reference)
#include <cuda_runtime.h>
#include <math.h>

#define T_LEN   8192
#define F_DIM   8
#define B_SZ    128
#define NLAGS   24
#define SEGS    8
#define SELEM   (T_LEN / SEGS)      // 1024 elements per segment
#define LOOK    NLAGS               // 24-element lookahead
#define LTOT    (SELEM + LOOK)      // 1048 loaded per CTA
#define THREADS 256
#define NWARPS  (THREADS / 32)      // 8
#define CHUNK   (SELEM / THREADS)   // 4
#define WIN     (CHUNK + NLAGS)     // 28-element register window

// per-row accumulators: [0]=S, [1]=Q, [2+l]=Sxy[l]
__device__ float g_rowacc[B_SZ][2 + NLAGS];   // zero-init at load; consumers re-zero
__device__ float g_ht[B_SZ][4];               // hs, hq, ts, tq (single writer each)
__device__ int   g_rowcnt[B_SZ];
__device__ float g_partials[B_SZ];
__device__ int   g_count = 0;

__device__ __forceinline__ int zi(int t) { return t + (t >> 5); }

__global__ __launch_bounds__(THREADS)
void autocorr_seg_kernel(const float* __restrict__ input,
                         const float* __restrict__ lagw,
                         const float* __restrict__ seas,
                         float* __restrict__ out) {
    __shared__ float zs[LTOT + (LTOT >> 5) + 1];
    __shared__ float red[2 * NWARPS];
    __shared__ float warp_sxy[NWARPS][NLAGS];

    const int cta  = blockIdx.x;
    const int b    = cta >> 3;          // row
    const int seg  = cta & (SEGS - 1);  // segment within row
    const int tid  = threadIdx.x;
    const int warp = tid >> 5;
    const int lane = tid & 31;
    const int t0   = seg * SELEM;
    const float* row = input + (size_t)b * T_LEN * F_DIM;

    // ---- load segment + lookahead (stride-8 f0 column); S/Q over own 1024 ----
    float lsum = 0.f, lsq = 0.f;
    #pragma unroll
    for (int k = 0; k < 5; k++) {
        int idx = tid + k * THREADS;
        if (idx < LTOT) {
            int t = t0 + idx;
            float v = (t < T_LEN) ? __ldg(row + (size_t)t * F_DIM) : 0.f;
            zs[zi(idx)] = v;
            if (idx < SELEM) { lsum += v; lsq += v * v; }
        }
    }
    #pragma unroll
    for (int o = 16; o > 0; o >>= 1) {
        lsum += __shfl_xor_sync(0xffffffffu, lsum, o);
        lsq  += __shfl_xor_sync(0xffffffffu, lsq,  o);
    }
    if (lane == 0) { red[warp] = lsum; red[NWARPS + warp] = lsq; }

    __syncthreads();

    // ---- cross-products from a 28-elem register window ----
    float w[WIN];
    const int i0 = tid * CHUNK;
    #pragma unroll
    for (int j = 0; j < WIN; j++) w[j] = zs[zi(i0 + j)];   // max 1047, in-bounds
    float acc[NLAGS];
    #pragma unroll
    for (int l = 0; l < NLAGS; l++) acc[l] = 0.f;
    #pragma unroll
    for (int j = 0; j < CHUNK; j++) {
        #pragma unroll
        for (int l = 0; l < NLAGS; l++)
            acc[l] = fmaf(w[j], w[j + l + 1], acc[l]);
    }
    #pragma unroll
    for (int l = 0; l < NLAGS; l++) {
        float v = acc[l];
        #pragma unroll
        for (int o = 16; o > 0; o >>= 1)
            v += __shfl_xor_sync(0xffffffffu, v, o);
        if (lane == 0) warp_sxy[warp][l] = v;
    }
    __syncthreads();

    // ---- warp 0: fold CTA partials into per-row accumulators ----
    if (warp == 0) {
        if (lane < NLAGS) {
            float v = 0.f;
            #pragma unroll
            for (int wi = 0; wi < NWARPS; wi++) v += warp_sxy[wi][lane];
            atomicAdd(&g_rowacc[b][2 + lane], v);
        } else if (lane == 24) {
            float S = 0.f;
            #pragma unroll
            for (int i = 0; i < NWARPS; i++) S += red[i];
            atomicAdd(&g_rowacc[b][0], S);
        } else if (lane == 25) {
            float Q = 0.f;
            #pragma unroll
            for (int i = 0; i < NWARPS; i++) Q += red[NWARPS + i];
            atomicAdd(&g_rowacc[b][1], Q);
        }

        // head/tail partial sums (single writer: seg 0 / seg 7)
        if (seg == 0) {
            float v = (lane < NLAGS) ? zs[zi(lane)] : 0.f;
            float s = v, q = v * v;
            #pragma unroll
            for (int o = 16; o > 0; o >>= 1) {
                s += __shfl_xor_sync(0xffffffffu, s, o);
                q += __shfl_xor_sync(0xffffffffu, q, o);
            }
            // note: these are sums over the FULL 24; per-lag prefixes handled below
            if (lane == 0) { g_ht[b][0] = 0.f; }   // placeholder; real per-lag work in finalizer
        }

        __threadfence();
        __syncwarp();

        int tk = 0;
        if (lane == 0) tk = atomicAdd(&g_rowcnt[b], 1);
        tk = __shfl_sync(0xffffffffu, tk, 0);

        if (tk == SEGS - 1) {   // last segment of row b: finalize this row
            __threadfence();
            // softmax(lag_weights) across lanes 0..23
            float e = (lane < NLAGS) ? __expf(__ldg(lagw + lane)) : 0.f;
            float se = e;
            #pragma unroll
            for (int o = 16; o > 0; o >>= 1) se += __shfl_xor_sync(0xffffffffu, se, o);
            float coef = e / se;
            if (lane == 11) coef += __ldg(seas + 0);
            if (lane == 23) coef += __ldg(seas + 1);

            float val = 0.f;
            if (lane < NLAGS) {
                const int lag = lane + 1;
                float S   = g_rowacc[b][0];
                float Q   = g_rowacc[b][1];
                float sxy = g_rowacc[b][2 + lane];

                // per-lag head/tail sums straight from global input (<=24 strided loads)
                float hs = 0.f, hq = 0.f, ts = 0.f, tq = 0.f;
                for (int t = 0; t < lag; t++) {
                    float v = __ldg(row + (size_t)t * F_DIM);
                    hs += v; hq += v * v;
                }
                for (int t = T_LEN - lag; t < T_LEN; t++) {
                    float v = __ldg(row + (size_t)t * F_DIM);
                    ts += v; tq += v * v;
                }

                const float Sx  = S - ts,  Sy  = S - hs;
                const float Sxx = Q - tq,  Syy = Q - hq;
                const float n   = (float)(T_LEN - lag);

                float num = sxy - Sx * Sy / n;
                float vx  = Sxx - Sx * Sx / n;
                float vy  = Syy - Sy * Sy / n;
                float r   = num / (sqrtf(fmaxf(vx, 0.f)) * sqrtf(fmaxf(vy, 0.f)));
                r = fminf(1.f, fmaxf(-1.f, r));
                val = r * coef;
            }
            #pragma unroll
            for (int o = 16; o > 0; o >>= 1) val += __shfl_xor_sync(0xffffffffu, val, o);

            // reset row state for next graph replay
            if (lane < 2 + NLAGS) g_rowacc[b][lane] = 0.f;
            if (lane == 1) g_rowcnt[b] = 0;

            int gt = 0;
            if (lane == 0) {
                g_partials[b] = val;
                __threadfence();
                gt = atomicAdd(&g_count, 1);
            }
            gt = __shfl_sync(0xffffffffu, gt, 0);

            if (gt == B_SZ - 1) {   // last row folds the global mean
                __threadfence();
                float s = g_partials[lane] + g_partials[lane + 32]
                        + g_partials[lane + 64] + g_partials[lane + 96];
                #pragma unroll
                for (int o = 16; o > 0; o >>= 1) s += __shfl_xor_sync(0xffffffffu, s, o);
                if (lane == 0) {
                    out[0] = s * (1.f / (float)B_SZ);
                    g_count = 0;
                }
            }
        }
    }
}

extern "C" void kernel_launch(void* const* d_in, const int* in_sizes, int n_in,
                              void* d_out, int out_size) {
    const float* input = (const float*)d_in[0];   // input_sequence (128,8192,8)
    // d_in[1] = hidden_states — never referenced by the math; intentionally unused
    const float* lagw  = (const float*)d_in[2];   // lag_weights (24,)
    const float* seas  = (const float*)d_in[3];   // seasonal_importance (2,)
    float* out = (float*)d_out;

    autocorr_seg_kernel<<<B_SZ * SEGS, THREADS>>>(input, lagw, seas, out);
}

// round 10
// speedup vs baseline: 2.1349x; 2.1349x over previous
#include <cuda_runtime.h>
#include <math.h>
#include <stdint.h>

#define T_LEN   8192
#define F_DIM   8
#define B_SZ    128
#define NLAGS   24
#define THREADS 256
#define NWARPS  (THREADS / 32)      // 8
#define CHUNK   (T_LEN / THREADS)   // 32
#define WIN     (CHUNK + NLAGS)     // 56-element register window

#define NSTAGE  6
#define CELEM   512                         // elements per chunk
#define CFLOAT  (CELEM * F_DIM)             // 4096 floats
#define CBYTES  (CFLOAT * 4)                // 16384 bytes
#define NCHUNK  (T_LEN / CELEM)             // 16
#define DYN_SMEM ((NSTAGE * CFLOAT + T_LEN + (T_LEN >> 5)) * 4)   // 96KB + 33KB

__device__ float g_partials[B_SZ];
__device__ int   g_count = 0;

__device__ __forceinline__ int zi(int t) { return t + (t >> 5); }

__device__ __forceinline__ uint32_t s2u(const void* p) {
    return (uint32_t)__cvta_generic_to_shared(p);
}
__device__ __forceinline__ void mbar_init(uint32_t a, uint32_t cnt) {
    asm volatile("mbarrier.init.shared.b64 [%0], %1;" :: "r"(a), "r"(cnt) : "memory");
}
__device__ __forceinline__ void mbar_expect_tx(uint32_t a, uint32_t bytes) {
    asm volatile("mbarrier.arrive.expect_tx.shared.b64 _, [%0], %1;" :: "r"(a), "r"(bytes) : "memory");
}
__device__ __forceinline__ void bulk_g2s(uint32_t dst, const void* src, uint32_t bytes, uint32_t mbar) {
    asm volatile("cp.async.bulk.shared::cta.global.mbarrier::complete_tx::bytes [%0], [%1], %2, [%3];"
                 :: "r"(dst), "l"(src), "r"(bytes), "r"(mbar) : "memory");
}
__device__ __forceinline__ void mbar_wait(uint32_t a, uint32_t ph) {
    asm volatile(
        "{\n\t.reg .pred P;\n\t"
        "WL_%=:\n\t"
        "mbarrier.try_wait.parity.acquire.cta.shared::cta.b64 P, [%0], %1, 0x989680;\n\t"
        "@P bra.uni WD_%=;\n\t"
        "bra.uni WL_%=;\n\t"
        "WD_%=:\n\t}"
        :: "r"(a), "r"(ph) : "memory");
}

__global__ __launch_bounds__(THREADS)
void autocorr_kernel(const float* __restrict__ input,
                     const float* __restrict__ lagw,
                     const float* __restrict__ seas,
                     float* __restrict__ out) {
    extern __shared__ float dyn[];
    float* buf = dyn;                       // [NSTAGE][CFLOAT] raw chunks
    float* zs  = dyn + NSTAGE * CFLOAT;     // padded f0 column

    __shared__ float red[2 * NWARPS];
    __shared__ float warp_sxy[NWARPS][NLAGS];
    __shared__ alignas(16) uint64_t mb[NSTAGE];

    const int b    = blockIdx.x;
    const int tid  = threadIdx.x;
    const int warp = tid >> 5;
    const int lane = tid & 31;
    const char* rowb = (const char*)(input + (size_t)b * T_LEN * F_DIM);
    const uint32_t bufu = s2u(buf);

    if (tid == 0) {
        #pragma unroll
        for (int s = 0; s < NSTAGE; s++) mbar_init(s2u(&mb[s]), 1);
        asm volatile("fence.proxy.async.shared::cta;" ::: "memory");
    }
    __syncthreads();

    // ---- prologue: fill all 6 stages (≈96KB in flight) ----
    if (tid == 0) {
        #pragma unroll
        for (int s = 0; s < NSTAGE; s++) {
            uint32_t m = s2u(&mb[s]);
            mbar_expect_tx(m, CBYTES);
            bulk_g2s(bufu + s * CBYTES, rowb + (size_t)s * CBYTES, CBYTES, m);
        }
    }

    // ---- streaming loop: wait stage, extract f0, reissue stage for c+6 ----
    float lsum = 0.f, lsq = 0.f;
    #pragma unroll
    for (int c = 0; c < NCHUNK; c++) {
        const int s   = c % NSTAGE;
        const int par = (c / NSTAGE) & 1;
        mbar_wait(s2u(&mb[s]), par);

        const float4* b4 = (const float4*)(buf + s * CFLOAT);
        #pragma unroll
        for (int k = 0; k < CELEM / THREADS; k++) {
            int m = tid + k * THREADS;          // element within chunk
            float v = b4[2 * m].x;              // f0 lives at float4 index 2m
            zs[zi(c * CELEM + m)] = v;
            lsum += v;
            lsq  += v * v;
        }
        __syncthreads();                        // stage fully consumed

        if (tid == 0 && c + NSTAGE < NCHUNK) {
            asm volatile("fence.proxy.async.shared::cta;" ::: "memory");
            uint32_t m = s2u(&mb[s]);
            mbar_expect_tx(m, CBYTES);
            bulk_g2s(bufu + s * CBYTES, rowb + (size_t)(c + NSTAGE) * CBYTES, CBYTES, m);
        }
    }

    #pragma unroll
    for (int o = 16; o > 0; o >>= 1) {
        lsum += __shfl_xor_sync(0xffffffffu, lsum, o);
        lsq  += __shfl_xor_sync(0xffffffffu, lsq,  o);
    }
    if (lane == 0) { red[warp] = lsum; red[NWARPS + warp] = lsq; }
    __syncthreads();

    // ---- cross-products from a 56-elem register window (raw data:
    //      Pearson per window is invariant to the global normalization) ----
    float w[WIN];
    const int i0 = tid * CHUNK;
    #pragma unroll
    for (int j = 0; j < WIN; j++) {
        int idx = i0 + j;
        w[j] = (idx < T_LEN) ? zs[zi(idx)] : 0.f;
    }
    float acc[NLAGS];
    #pragma unroll
    for (int l = 0; l < NLAGS; l++) acc[l] = 0.f;
    #pragma unroll
    for (int j = 0; j < CHUNK; j++) {
        #pragma unroll
        for (int l = 0; l < NLAGS; l++)
            acc[l] = fmaf(w[j], w[j + l + 1], acc[l]);
    }

    #pragma unroll
    for (int l = 0; l < NLAGS; l++) {
        float v = acc[l];
        #pragma unroll
        for (int o = 16; o > 0; o >>= 1)
            v += __shfl_xor_sync(0xffffffffu, v, o);
        if (lane == 0) warp_sxy[warp][l] = v;
    }
    __syncthreads();

    // ---- epilogue: one warp finishes the whole row ----
    if (warp == 0) {
        float e = (lane < NLAGS) ? __expf(__ldg(lagw + lane)) : 0.f;
        float se = e;
        #pragma unroll
        for (int o = 16; o > 0; o >>= 1) se += __shfl_xor_sync(0xffffffffu, se, o);
        float coef = e / se;
        if (lane == 11) coef += __ldg(seas + 0);   // lag 12
        if (lane == 23) coef += __ldg(seas + 1);   // lag 24

        float val = 0.f;
        if (lane < NLAGS) {
            const int l   = lane;
            const int lag = l + 1;
            float sxy = 0.f;
            #pragma unroll
            for (int wi = 0; wi < NWARPS; wi++) sxy += warp_sxy[wi][l];

            float S = 0.f, Q = 0.f;
            #pragma unroll
            for (int i = 0; i < NWARPS; i++) { S += red[i]; Q += red[NWARPS + i]; }

            float hs = 0.f, hq = 0.f, ts = 0.f, tq = 0.f;
            for (int t = 0; t < lag; t++)            { float v = zs[zi(t)]; hs += v; hq += v * v; }
            for (int t = T_LEN - lag; t < T_LEN; t++){ float v = zs[zi(t)]; ts += v; tq += v * v; }

            const float Sx  = S - ts,  Sy  = S - hs;
            const float Sxx = Q - tq,  Syy = Q - hq;
            const float n   = (float)(T_LEN - lag);

            float num = sxy - Sx * Sy / n;
            float vx  = Sxx - Sx * Sx / n;
            float vy  = Syy - Sy * Sy / n;
            float r   = num / (sqrtf(fmaxf(vx, 0.f)) * sqrtf(fmaxf(vy, 0.f)));
            r = fminf(1.f, fmaxf(-1.f, r));
            val = r * coef;
        }
        #pragma unroll
        for (int o = 16; o > 0; o >>= 1) val += __shfl_xor_sync(0xffffffffu, val, o);

        int ticket = 0;
        if (lane == 0) {
            g_partials[b] = val;
            __threadfence();
            ticket = atomicAdd(&g_count, 1);
        }
        ticket = __shfl_sync(0xffffffffu, ticket, 0);

        if (ticket == B_SZ - 1) {   // last block folds the 128 row partials
            __threadfence();
            float s = g_partials[lane] + g_partials[lane + 32]
                    + g_partials[lane + 64] + g_partials[lane + 96];
            #pragma unroll
            for (int o = 16; o > 0; o >>= 1) s += __shfl_xor_sync(0xffffffffu, s, o);
            if (lane == 0) {
                out[0] = s * (1.f / (float)B_SZ);
                g_count = 0;   // reset for next graph replay
            }
        }
    }
}

extern "C" void kernel_launch(void* const* d_in, const int* in_sizes, int n_in,
                              void* d_out, int out_size) {
    const float* input = (const float*)d_in[0];   // input_sequence (128,8192,8)
    // d_in[1] = hidden_states — never referenced by the math; intentionally unused
    const float* lagw  = (const float*)d_in[2];   // lag_weights (24,)
    const float* seas  = (const float*)d_in[3];   // seasonal_importance (2,)
    float* out = (float*)d_out;

    cudaFuncSetAttribute(autocorr_kernel,
                         cudaFuncAttributeMaxDynamicSharedMemorySize, DYN_SMEM);
    autocorr_kernel<<<B_SZ, THREADS, DYN_SMEM>>>(input, lagw, seas, out);
}